// round 5
// baseline (speedup 1.0000x reference)
#include <cuda_runtime.h>
#include <cuda_bf16.h>

// Problem constants (dataset is fixed; runtime values are read from in_sizes
// and must not exceed these static scratch capacities).
#define NMAX   100000
#define EMAX   1250000
#define DIM    64          // feature dim (D == H == 64)
#define NGRAPH 512

// Scratch (allocation-free rule: __device__ globals). All declared as float4
// so every 128-bit access is 16B-aligned by type.
__device__ float4 g_agg  [NMAX   * (DIM / 4)];   // 25.6 MB
__device__ float4 g_h    [NMAX   * (DIM / 4)];   // 25.6 MB
__device__ float4 g_pool [NGRAPH * (DIM / 4)];
__device__ float4 g_cnt4 [NGRAPH / 4];           // counts (aliased as float[512])

// ---------------------------------------------------------------------------
// No-return vectorized global reductions (sm_90+): avoids the read-modify-
// write round trip of atomicAdd and moves 16B per op instead of 4B.
// ---------------------------------------------------------------------------
__device__ __forceinline__ void red_add_v4(float4* addr, float4 v) {
    asm volatile("red.global.add.v4.f32 [%0], {%1, %2, %3, %4};"
                 :: "l"(addr), "f"(v.x), "f"(v.y), "f"(v.z), "f"(v.w)
                 : "memory");
}
__device__ __forceinline__ void red_add_f32(float* addr, float v) {
    asm volatile("red.global.add.f32 [%0], %1;"
                 :: "l"(addr), "f"(v) : "memory");
}

// Branch-free index guard: any out-of-range index maps to 0 instead of
// generating an illegal address. Costs ~2 ALU ops; converts a dtype/layout
// misunderstanding into a finite rel_err diagnostic instead of an IMA.
__device__ __forceinline__ int guard_idx(int i, int n) {
    return ((unsigned)i < (unsigned)n) ? i : 0;
}

// ---------------------------------------------------------------------------
// Zero fill (float4 stores; all targets are float4-typed globals)
// ---------------------------------------------------------------------------
__global__ void zero_kernel(float4* __restrict__ p, int n4) {
    int i = blockIdx.x * blockDim.x + threadIdx.x;
    int stride = gridDim.x * blockDim.x;
    float4 z = make_float4(0.f, 0.f, 0.f, 0.f);
    for (; i < n4; i += stride) p[i] = z;
}

// ---------------------------------------------------------------------------
// Edge scatter: agg[dst] += feat[src] * w      (one thread per (edge, float4))
// 16 consecutive lanes handle one edge => the 256B gather per edge is fully
// coalesced; the redundant src/dst/w loads broadcast through L1.
// Indices are INT32 (JAX demotes int64 randint without x64 enabled).
// ---------------------------------------------------------------------------
__global__ void scatter_kernel(const float4* __restrict__ feat,
                               const int* __restrict__ src,
                               const int* __restrict__ dst,
                               const float* __restrict__ w,
                               float4* __restrict__ agg,
                               int E, int N) {
    int t = blockIdx.x * blockDim.x + threadIdx.x;
    if (t >= E * 16) return;
    int e = t >> 4;
    int j = t & 15;
    int s = guard_idx(src[e], N);
    int d = guard_idx(dst[e], N);
    float ww = w[e];
    float4 v = feat[(size_t)s * 16 + j];
    v.x *= ww; v.y *= ww; v.z *= ww; v.w *= ww;
    red_add_v4(&agg[(size_t)d * 16 + j], v);
}

// ---------------------------------------------------------------------------
// Fused node transform:
//   out = leaky_relu( agg @ W_rel + x @ W_root + b )
// One thread per node, 64 fp32 accumulators, both 64x64 weight matrices
// resident in smem (uniform broadcast reads, N=1 conflict degree).
// MODE 0: write result rows to `out`.
// MODE 1: fused global-mean-pool epilogue (red.v4 into g_pool by graph id,
//         red count into g_cnt). h2 never touches memory.
// ---------------------------------------------------------------------------
template <int MODE>
__global__ __launch_bounds__(128)
void node_gemm_kernel(const float4* __restrict__ xin,
                      const float4* __restrict__ agg,
                      const float*  __restrict__ Wroot,
                      const float*  __restrict__ Wrel,
                      const float*  __restrict__ bias,
                      float4* __restrict__ out,
                      const int* __restrict__ batch,
                      int Nn) {
    __shared__ float4 sWr[64 * 16];
    __shared__ float4 sWe[64 * 16];
    __shared__ float  sb[64];

    const float4* Wr4 = (const float4*)Wroot;
    const float4* We4 = (const float4*)Wrel;
    for (int i = threadIdx.x; i < 1024; i += 128) {
        sWr[i] = Wr4[i];
        sWe[i] = We4[i];
    }
    if (threadIdx.x < 64) sb[threadIdx.x] = bias[threadIdx.x];
    __syncthreads();

    int n = blockIdx.x * 128 + threadIdx.x;
    if (n >= Nn) return;

    float acc[64];
#pragma unroll
    for (int j = 0; j < 64; j++) acc[j] = sb[j];

    const float4* xr = xin + (size_t)n * 16;
    const float4* ar = agg + (size_t)n * 16;

#pragma unroll 1
    for (int kk = 0; kk < 16; kk++) {           // keep rolled: icache friendly
        float4 xv = xr[kk];
        float4 av = ar[kk];
#pragma unroll
        for (int dk = 0; dk < 4; dk++) {
            float xs = (&xv.x)[dk];
            float as = (&av.x)[dk];
            int k = 4 * kk + dk;
#pragma unroll
            for (int jj = 0; jj < 16; jj++) {
                float4 wv = sWr[k * 16 + jj];
                float4 ev = sWe[k * 16 + jj];
                acc[4 * jj + 0] = fmaf(xs, wv.x, fmaf(as, ev.x, acc[4 * jj + 0]));
                acc[4 * jj + 1] = fmaf(xs, wv.y, fmaf(as, ev.y, acc[4 * jj + 1]));
                acc[4 * jj + 2] = fmaf(xs, wv.z, fmaf(as, ev.z, acc[4 * jj + 2]));
                acc[4 * jj + 3] = fmaf(xs, wv.w, fmaf(as, ev.w, acc[4 * jj + 3]));
            }
        }
    }

#pragma unroll
    for (int j = 0; j < 64; j++) {
        float v = acc[j];
        acc[j] = v > 0.f ? v : 0.01f * v;       // leaky relu, slope 0.01
    }

    if (MODE == 0) {
        float4* o = out + (size_t)n * 16;
#pragma unroll
        for (int jj = 0; jj < 16; jj++)
            o[jj] = make_float4(acc[4 * jj + 0], acc[4 * jj + 1],
                                acc[4 * jj + 2], acc[4 * jj + 3]);
    } else {
        int b = guard_idx(batch[n], NGRAPH);
        float4* pr = g_pool + (size_t)b * 16;
#pragma unroll
        for (int jj = 0; jj < 16; jj++)
            red_add_v4(&pr[jj], make_float4(acc[4 * jj + 0], acc[4 * jj + 1],
                                            acc[4 * jj + 2], acc[4 * jj + 3]));
        red_add_f32(((float*)g_cnt4) + b, 1.0f);
    }
}

// ---------------------------------------------------------------------------
// Final: out[g] = (pool[g] / max(cnt[g],1)) @ Wl + bl     (512 x 64 x 8)
// ---------------------------------------------------------------------------
__global__ void final_kernel(const float* __restrict__ Wl,
                             const float* __restrict__ bl,
                             float* __restrict__ out) {
    __shared__ float sW[64 * 8];
    __shared__ float sb2[8];
    int t = threadIdx.x;                 // blockDim.x == 512
    sW[t] = Wl[t];
    if (t < 8) sb2[t] = bl[t];
    __syncthreads();

    int g = t;
    float cnt = ((const float*)g_cnt4)[g];
    float inv = 1.0f / fmaxf(cnt, 1.0f);
    const float* pr = (const float*)(g_pool + (size_t)g * 16);

    float acc[8];
#pragma unroll
    for (int j = 0; j < 8; j++) acc[j] = sb2[j];
#pragma unroll 4
    for (int k = 0; k < 64; k++) {
        float p = pr[k] * inv;
#pragma unroll
        for (int j = 0; j < 8; j++)
            acc[j] = fmaf(p, sW[k * 8 + j], acc[j]);
    }
#pragma unroll
    for (int j = 0; j < 8; j++) out[g * 8 + j] = acc[j];
}

// ---------------------------------------------------------------------------
// Launch sequence (graph-capturable: kernels only)
// ---------------------------------------------------------------------------
extern "C" void kernel_launch(void* const* d_in, const int* in_sizes, int n_in,
                              void* d_out, int out_size) {
    const float4* x      = (const float4*)d_in[0];
    const int*    ei     = (const int*)d_in[1];     // [2, E] int32 (JAX demotes i64)
    const float*  w      = (const float*)d_in[2];
    const int*    batch  = (const int*)d_in[3];     // int32
    const float*  W1root = (const float*)d_in[4];
    const float*  W1rel  = (const float*)d_in[5];
    const float*  b1     = (const float*)d_in[6];
    const float*  W2root = (const float*)d_in[7];
    const float*  W2rel  = (const float*)d_in[8];
    const float*  b2     = (const float*)d_in[9];
    const float*  Wl     = (const float*)d_in[10];
    const float*  bl     = (const float*)d_in[11];
    float*        out    = (float*)d_out;

    int N = in_sizes[0] / DIM;        // 100000
    int E = in_sizes[2];              // 1250000
    if (N > NMAX) N = NMAX;
    if (E > EMAX) E = EMAX;
    const int* src = ei;
    const int* dst = ei + E;

    float4 *agg, *h, *pool, *cnt4;
    cudaGetSymbolAddress((void**)&agg,  g_agg);
    cudaGetSymbolAddress((void**)&h,    g_h);
    cudaGetSymbolAddress((void**)&pool, g_pool);
    cudaGetSymbolAddress((void**)&cnt4, g_cnt4);

    int aggN4   = N * 16;
    int zeroBlk = (aggN4 + 255) / 256;
    int scatTot = E * 16;
    int scatBlk = (scatTot + 255) / 256;
    int gemmBlk = (N + 127) / 128;

    // Layer 1
    zero_kernel<<<zeroBlk, 256>>>(agg, aggN4);
    zero_kernel<<<(NGRAPH * 16 + 255) / 256, 256>>>(pool, NGRAPH * 16);
    zero_kernel<<<1, 128>>>(cnt4, NGRAPH / 4);
    scatter_kernel<<<scatBlk, 256>>>(x, src, dst, w, agg, E, N);
    node_gemm_kernel<0><<<gemmBlk, 128>>>(x, agg, W1root, W1rel, b1,
                                          h, nullptr, N);
    // Layer 2 (+ fused mean-pool accumulation)
    zero_kernel<<<zeroBlk, 256>>>(agg, aggN4);
    scatter_kernel<<<scatBlk, 256>>>(h, src, dst, w, agg, E, N);
    node_gemm_kernel<1><<<gemmBlk, 128>>>(h, agg, W2root, W2rel, b2,
                                          nullptr, batch, N);
    // Readout
    final_kernel<<<1, 512>>>(Wl, bl, out);
}

// round 6
// speedup vs baseline: 1.6399x; 1.6399x over previous
#include <cuda_runtime.h>
#include <cuda_bf16.h>

// Problem constants (dataset fixed; runtime values clamped to these).
#define NMAX   100000
#define EMAX   1250000
#define DIM    64
#define NGRAPH 512
#define SCAN_BLK 1024
#define NB_MAX   128    // ceil(NMAX/SCAN_BLK) = 98 <= 128

// ---------------- scratch (__device__ globals; allocation-free rule) -------
__device__ float4 g_agg  [NMAX   * (DIM / 4)];   // 25.6 MB
__device__ float4 g_h    [NMAX   * (DIM / 4)];   // 25.6 MB
__device__ float4 g_pool [NGRAPH * (DIM / 4)];
__device__ float4 g_cnt4 [NGRAPH / 4];
// CSR scratch
__device__ int   g_deg   [NMAX];
__device__ int   g_cursor[NMAX];
__device__ int   g_off   [NMAX + 1];
__device__ int   g_bsum  [NB_MAX];
__device__ int   g_boff  [NB_MAX];
__device__ int   g_psrc  [EMAX];
__device__ float g_pw    [EMAX];

// ---------------------------------------------------------------------------
__device__ __forceinline__ void red_add_v4(float4* addr, float4 v) {
    asm volatile("red.global.add.v4.f32 [%0], {%1, %2, %3, %4};"
                 :: "l"(addr), "f"(v.x), "f"(v.y), "f"(v.z), "f"(v.w)
                 : "memory");
}
__device__ __forceinline__ void red_add_f32(float* addr, float v) {
    asm volatile("red.global.add.f32 [%0], %1;"
                 :: "l"(addr), "f"(v) : "memory");
}
__device__ __forceinline__ int guard_idx(int i, int n) {
    return ((unsigned)i < (unsigned)n) ? i : 0;
}

// ---------------------------------------------------------------------------
// Fills / zeros
// ---------------------------------------------------------------------------
__global__ void zero_f4_kernel(float4* __restrict__ p, int n4) {
    int i = blockIdx.x * blockDim.x + threadIdx.x;
    int stride = gridDim.x * blockDim.x;
    float4 z = make_float4(0.f, 0.f, 0.f, 0.f);
    for (; i < n4; i += stride) p[i] = z;
}
__global__ void zero_i_kernel(int* __restrict__ a, int* __restrict__ b, int n) {
    int i = blockIdx.x * blockDim.x + threadIdx.x;
    if (i < n) { a[i] = 0; b[i] = 0; }
}

// ---------------------------------------------------------------------------
// CSR build: histogram -> 3-phase exclusive scan -> bucket fill
// ---------------------------------------------------------------------------
__global__ void hist_kernel(const int* __restrict__ dst, int E, int N,
                            int* __restrict__ deg) {
    int e = blockIdx.x * blockDim.x + threadIdx.x;
    if (e < E) atomicAdd(&deg[guard_idx(dst[e], N)], 1);
}

__global__ void scanA_kernel(const int* __restrict__ deg, int* __restrict__ off,
                             int* __restrict__ bsum, int N) {
    __shared__ int s[SCAN_BLK];
    int tx = threadIdx.x;
    int i = blockIdx.x * SCAN_BLK + tx;
    int v = (i < N) ? deg[i] : 0;
    s[tx] = v;
    __syncthreads();
    for (int d = 1; d < SCAN_BLK; d <<= 1) {
        int t = (tx >= d) ? s[tx - d] : 0;
        __syncthreads();
        s[tx] += t;
        __syncthreads();
    }
    if (i < N) off[i] = s[tx] - v;                 // exclusive within block
    if (tx == SCAN_BLK - 1) bsum[blockIdx.x] = s[tx];
}

__global__ void scanB_kernel(const int* __restrict__ bsum, int* __restrict__ boff,
                             int nb, int* __restrict__ off_last, int E) {
    __shared__ int s[NB_MAX];
    int tx = threadIdx.x;                          // blockDim.x == NB_MAX
    int v = (tx < nb) ? bsum[tx] : 0;
    s[tx] = v;
    __syncthreads();
    for (int d = 1; d < NB_MAX; d <<= 1) {
        int t = (tx >= d) ? s[tx - d] : 0;
        __syncthreads();
        s[tx] += t;
        __syncthreads();
    }
    if (tx < nb) boff[tx] = s[tx] - v;
    if (tx == 0) *off_last = E;                    // off[N] = E
}

__global__ void scanC_kernel(int* __restrict__ off, const int* __restrict__ boff,
                             int N) {
    int i = blockIdx.x * blockDim.x + threadIdx.x;
    if (i < N) off[i] += boff[i >> 10];
}

__global__ void fill_kernel(const int* __restrict__ src, const int* __restrict__ dst,
                            const float* __restrict__ w,
                            const int* __restrict__ off, int* __restrict__ cursor,
                            int* __restrict__ psrc, float* __restrict__ pw,
                            int E, int N) {
    int e = blockIdx.x * blockDim.x + threadIdx.x;
    if (e >= E) return;
    int d = guard_idx(dst[e], N);
    int pos = atomicAdd(&cursor[d], 1);
    int slot = off[d] + pos;
    psrc[slot] = guard_idx(src[e], N);
    pw[slot] = w[e];
}

// ---------------------------------------------------------------------------
// CSR aggregation: one warp per dst row. Half-warp h processes edges
// beg+h, beg+h+2, ...; lane j of a half-warp owns float4 column j of the
// 64-wide feature row (256B coalesced gather per edge). Register
// accumulation; halves merged with 4 shfl.xor; single plain store.
// Replaces 320 MB of L2 atomic RMW with a 25.6 MB write.
// ---------------------------------------------------------------------------
__global__ __launch_bounds__(256)
void agg_csr_kernel(const float4* __restrict__ feat,
                    const int* __restrict__ off,
                    const int* __restrict__ psrc,
                    const float* __restrict__ pw,
                    float4* __restrict__ agg, int N) {
    int warp = (blockIdx.x * blockDim.x + threadIdx.x) >> 5;
    if (warp >= N) return;
    int lane = threadIdx.x & 31;
    int half = lane >> 4;
    int j = lane & 15;

    int beg = off[warp];
    int end = off[warp + 1];

    float4 acc = make_float4(0.f, 0.f, 0.f, 0.f);
    for (int i = beg + half; i < end; i += 2) {
        int s = psrc[i];
        float ww = pw[i];
        float4 v = feat[(size_t)s * 16 + j];
        acc.x = fmaf(v.x, ww, acc.x);
        acc.y = fmaf(v.y, ww, acc.y);
        acc.z = fmaf(v.z, ww, acc.z);
        acc.w = fmaf(v.w, ww, acc.w);
    }
    acc.x += __shfl_xor_sync(0xffffffffu, acc.x, 16);
    acc.y += __shfl_xor_sync(0xffffffffu, acc.y, 16);
    acc.z += __shfl_xor_sync(0xffffffffu, acc.z, 16);
    acc.w += __shfl_xor_sync(0xffffffffu, acc.w, 16);
    if (half == 0) agg[(size_t)warp * 16 + j] = acc;
}

// ---------------------------------------------------------------------------
// Fused node transform: out = leaky_relu(agg @ W_rel + x @ W_root + b)
// MODE 0: write rows. MODE 1: fused mean-pool accumulation (red.v4).
// ---------------------------------------------------------------------------
template <int MODE>
__global__ __launch_bounds__(128)
void node_gemm_kernel(const float4* __restrict__ xin,
                      const float4* __restrict__ agg,
                      const float*  __restrict__ Wroot,
                      const float*  __restrict__ Wrel,
                      const float*  __restrict__ bias,
                      float4* __restrict__ out,
                      const int* __restrict__ batch,
                      int Nn) {
    __shared__ float4 sWr[64 * 16];
    __shared__ float4 sWe[64 * 16];
    __shared__ float  sb[64];

    const float4* Wr4 = (const float4*)Wroot;
    const float4* We4 = (const float4*)Wrel;
    for (int i = threadIdx.x; i < 1024; i += 128) {
        sWr[i] = Wr4[i];
        sWe[i] = We4[i];
    }
    if (threadIdx.x < 64) sb[threadIdx.x] = bias[threadIdx.x];
    __syncthreads();

    int n = blockIdx.x * 128 + threadIdx.x;
    if (n >= Nn) return;

    float acc[64];
#pragma unroll
    for (int j = 0; j < 64; j++) acc[j] = sb[j];

    const float4* xr = xin + (size_t)n * 16;
    const float4* ar = agg + (size_t)n * 16;

#pragma unroll 1
    for (int kk = 0; kk < 16; kk++) {
        float4 xv = xr[kk];
        float4 av = ar[kk];
#pragma unroll
        for (int dk = 0; dk < 4; dk++) {
            float xs = (&xv.x)[dk];
            float as = (&av.x)[dk];
            int k = 4 * kk + dk;
#pragma unroll
            for (int jj = 0; jj < 16; jj++) {
                float4 wv = sWr[k * 16 + jj];
                float4 ev = sWe[k * 16 + jj];
                acc[4 * jj + 0] = fmaf(xs, wv.x, fmaf(as, ev.x, acc[4 * jj + 0]));
                acc[4 * jj + 1] = fmaf(xs, wv.y, fmaf(as, ev.y, acc[4 * jj + 1]));
                acc[4 * jj + 2] = fmaf(xs, wv.z, fmaf(as, ev.z, acc[4 * jj + 2]));
                acc[4 * jj + 3] = fmaf(xs, wv.w, fmaf(as, ev.w, acc[4 * jj + 3]));
            }
        }
    }

#pragma unroll
    for (int j = 0; j < 64; j++) {
        float v = acc[j];
        acc[j] = v > 0.f ? v : 0.01f * v;
    }

    if (MODE == 0) {
        float4* o = out + (size_t)n * 16;
#pragma unroll
        for (int jj = 0; jj < 16; jj++)
            o[jj] = make_float4(acc[4 * jj + 0], acc[4 * jj + 1],
                                acc[4 * jj + 2], acc[4 * jj + 3]);
    } else {
        int b = guard_idx(batch[n], NGRAPH);
        float4* pr = g_pool + (size_t)b * 16;
#pragma unroll
        for (int jj = 0; jj < 16; jj++)
            red_add_v4(&pr[jj], make_float4(acc[4 * jj + 0], acc[4 * jj + 1],
                                            acc[4 * jj + 2], acc[4 * jj + 3]));
        red_add_f32(((float*)g_cnt4) + b, 1.0f);
    }
}

// ---------------------------------------------------------------------------
// Final: out[g] = (pool[g] / max(cnt[g],1)) @ Wl + bl     (512 x 64 x 8)
// ---------------------------------------------------------------------------
__global__ void final_kernel(const float* __restrict__ Wl,
                             const float* __restrict__ bl,
                             float* __restrict__ out) {
    __shared__ float sW[64 * 8];
    __shared__ float sb2[8];
    int t = threadIdx.x;                 // blockDim.x == 512
    sW[t] = Wl[t];
    if (t < 8) sb2[t] = bl[t];
    __syncthreads();

    int g = t;
    float cnt = ((const float*)g_cnt4)[g];
    float inv = 1.0f / fmaxf(cnt, 1.0f);
    const float* pr = (const float*)(g_pool + (size_t)g * 16);

    float acc[8];
#pragma unroll
    for (int j = 0; j < 8; j++) acc[j] = sb2[j];
#pragma unroll 4
    for (int k = 0; k < 64; k++) {
        float p = pr[k] * inv;
#pragma unroll
        for (int j = 0; j < 8; j++)
            acc[j] = fmaf(p, sW[k * 8 + j], acc[j]);
    }
#pragma unroll
    for (int j = 0; j < 8; j++) out[g * 8 + j] = acc[j];
}

// ---------------------------------------------------------------------------
// Launch sequence (graph-capturable: kernels only)
// ---------------------------------------------------------------------------
extern "C" void kernel_launch(void* const* d_in, const int* in_sizes, int n_in,
                              void* d_out, int out_size) {
    const float4* x      = (const float4*)d_in[0];
    const int*    ei     = (const int*)d_in[1];     // [2, E] int32
    const float*  w      = (const float*)d_in[2];
    const int*    batch  = (const int*)d_in[3];     // int32
    const float*  W1root = (const float*)d_in[4];
    const float*  W1rel  = (const float*)d_in[5];
    const float*  b1     = (const float*)d_in[6];
    const float*  W2root = (const float*)d_in[7];
    const float*  W2rel  = (const float*)d_in[8];
    const float*  b2     = (const float*)d_in[9];
    const float*  Wl     = (const float*)d_in[10];
    const float*  bl     = (const float*)d_in[11];
    float*        out    = (float*)d_out;

    int N = in_sizes[0] / DIM;        // 100000
    int E = in_sizes[2];              // 1250000
    if (N > NMAX) N = NMAX;
    if (E > EMAX) E = EMAX;
    const int* src = ei;
    const int* dst = ei + E;

    float4 *agg, *h, *pool, *cnt4;
    int *deg, *cursor, *off, *bsum, *boff, *psrc;
    float *pw;
    cudaGetSymbolAddress((void**)&agg,    g_agg);
    cudaGetSymbolAddress((void**)&h,      g_h);
    cudaGetSymbolAddress((void**)&pool,   g_pool);
    cudaGetSymbolAddress((void**)&cnt4,   g_cnt4);
    cudaGetSymbolAddress((void**)&deg,    g_deg);
    cudaGetSymbolAddress((void**)&cursor, g_cursor);
    cudaGetSymbolAddress((void**)&off,    g_off);
    cudaGetSymbolAddress((void**)&bsum,   g_bsum);
    cudaGetSymbolAddress((void**)&boff,   g_boff);
    cudaGetSymbolAddress((void**)&psrc,   g_psrc);
    cudaGetSymbolAddress((void**)&pw,     g_pw);

    int nb      = (N + SCAN_BLK - 1) / SCAN_BLK;       // 98
    int eBlk    = (E + 255) / 256;
    int nBlk    = (N + 255) / 256;
    int gemmBlk = (N + 127) / 128;
    int aggBlk  = (N + 7) / 8;                         // 8 warps / block

    // ---- CSR build (once; shared by both layers) ----
    zero_i_kernel<<<nBlk, 256>>>(deg, cursor, N);
    hist_kernel<<<eBlk, 256>>>(dst, E, N, deg);
    scanA_kernel<<<nb, SCAN_BLK>>>(deg, off, bsum, N);
    scanB_kernel<<<1, NB_MAX>>>(bsum, boff, nb, off + N, E);
    scanC_kernel<<<nBlk, 256>>>(off, boff, N);
    fill_kernel<<<eBlk, 256>>>(src, dst, w, off, cursor, psrc, pw, E, N);

    // ---- pool scratch zero ----
    zero_f4_kernel<<<(NGRAPH * 16 + 255) / 256, 256>>>(pool, NGRAPH * 16);
    zero_f4_kernel<<<1, 128>>>(cnt4, NGRAPH / 4);

    // ---- Layer 1 ----
    agg_csr_kernel<<<aggBlk, 256>>>(x, off, psrc, pw, agg, N);
    node_gemm_kernel<0><<<gemmBlk, 128>>>(x, agg, W1root, W1rel, b1,
                                          h, nullptr, N);
    // ---- Layer 2 (+ fused mean-pool accumulation) ----
    agg_csr_kernel<<<aggBlk, 256>>>(h, off, psrc, pw, agg, N);
    node_gemm_kernel<1><<<gemmBlk, 128>>>(h, agg, W2root, W2rel, b2,
                                          nullptr, batch, N);
    // ---- Readout ----
    final_kernel<<<1, 512>>>(Wl, bl, out);
}